// round 1
// baseline (speedup 1.0000x reference)
#include <cuda_runtime.h>
#include <math_constants.h>

// Problem constants (from reference)
#define B_    32
#define C_    64
#define H_    64
#define W_    64
#define HW_   (H_*W_)          // 4096
#define CHW_  (C_*HW_)         // 262144
#define NPTS  (B_*HW_)         // 131072 points
#define K_    2048             // codebook entries
#define TPB   128              // threads per block == points per block
#define NBLK  (NPTS/TPB)       // 1024 blocks
#define TK    128              // codes per smem tile

// Scratch (no allocations allowed)
__device__ float g_ee[K_];          // ||e_k||^2
__device__ float g_partials[NBLK];  // per-block loss partial sums

// ---------------------------------------------------------------------------
// Precompute ||e_k||^2 (order irrelevant for argmin: contributes << ulp grid)
// ---------------------------------------------------------------------------
__global__ void ee_kernel(const float* __restrict__ ew) {
    int k = blockIdx.x * blockDim.x + threadIdx.x;
    if (k >= K_) return;
    const float4* r = reinterpret_cast<const float4*>(ew + (size_t)k * C_);
    float4 a = make_float4(0.f, 0.f, 0.f, 0.f);
#pragma unroll
    for (int c4 = 0; c4 < 16; c4++) {
        float4 e = r[c4];
        a.x = fmaf(e.x, e.x, a.x);
        a.y = fmaf(e.y, e.y, a.y);
        a.z = fmaf(e.z, e.z, a.z);
        a.w = fmaf(e.w, e.w, a.w);
    }
    g_ee[k] = (a.x + a.y) + (a.z + a.w);
}

// ---------------------------------------------------------------------------
// Main VQ kernel: one thread per spatial point, codebook tiled through smem.
// d_k = (zz + ee_k) - 2*dot_k  computed in fp32 exactly as the reference
// formula; argmin with strict '<' ascending k == first-occurrence tiebreak.
// ---------------------------------------------------------------------------
__global__ __launch_bounds__(TPB)
void vq_kernel(const float* __restrict__ z, const float* __restrict__ ew,
               float* __restrict__ out, int out_size)
{
    __shared__ float es[TK * C_];   // 32 KB code tile, [k][c] row-major
    __shared__ float see[TK];       // ||e||^2 for tile
    __shared__ float sred[TPB];
    __shared__ int   sidx[TPB];

    const int tid = threadIdx.x;
    const int p0  = blockIdx.x * TPB;          // first point of this block
    const int b   = p0 / HW_;
    const int hw0 = p0 - b * HW_;              // block spans 128 consecutive hw
    const float* zp = z + (size_t)b * CHW_ + (hw0 + tid);

    // Load this thread's point: 64 channels, stride HW_ (coalesced across tid)
    float4 zr[16];
#pragma unroll
    for (int c4 = 0; c4 < 16; c4++) {
        zr[c4].x = zp[(size_t)(4*c4 + 0) * HW_];
        zr[c4].y = zp[(size_t)(4*c4 + 1) * HW_];
        zr[c4].z = zp[(size_t)(4*c4 + 2) * HW_];
        zr[c4].w = zp[(size_t)(4*c4 + 3) * HW_];
    }

    // zz = ||z||^2 (accumulation order is argmin-invariant: uniform ulp shift)
    float4 az = make_float4(0.f, 0.f, 0.f, 0.f);
#pragma unroll
    for (int c4 = 0; c4 < 16; c4++) {
        az.x = fmaf(zr[c4].x, zr[c4].x, az.x);
        az.y = fmaf(zr[c4].y, zr[c4].y, az.y);
        az.z = fmaf(zr[c4].z, zr[c4].z, az.z);
        az.w = fmaf(zr[c4].w, zr[c4].w, az.w);
    }
    const float zz = (az.x + az.y) + (az.z + az.w);

    float best = CUDART_INF_F;
    int   bidx = 0;

    for (int k0 = 0; k0 < K_; k0 += TK) {
        __syncthreads();   // protect previous tile's readers
        // Cooperative coalesced tile load (stores are conflict-free: consecutive)
#pragma unroll 8
        for (int j = 0; j < (TK * C_) / TPB; j++)
            es[j * TPB + tid] = ew[(size_t)k0 * C_ + j * TPB + tid];
        if (tid < TK) see[tid] = g_ee[k0 + tid];
        __syncthreads();

#pragma unroll 2
        for (int k = 0; k < TK; k++) {
            const float4* er = reinterpret_cast<const float4*>(es + k * C_);
            float4 a = make_float4(0.f, 0.f, 0.f, 0.f);
#pragma unroll
            for (int c4 = 0; c4 < 16; c4++) {
                float4 e = er[c4];   // broadcast LDS.128 (same addr whole warp)
                a.x = fmaf(zr[c4].x, e.x, a.x);
                a.y = fmaf(zr[c4].y, e.y, a.y);
                a.z = fmaf(zr[c4].z, e.z, a.z);
                a.w = fmaf(zr[c4].w, e.w, a.w);
            }
            float dot = (a.x + a.y) + (a.z + a.w);
            float d   = (zz + see[k]) - 2.0f * dot;   // exact reference ordering
            if (d < best) { best = d; bidx = k0 + k; } // strict < == first min
        }
    }

    sidx[tid] = bidx;

    // Commitment-loss partial: sum_c (e[bidx][c] - z[c])^2, fixed order
    const float4* erow = reinterpret_cast<const float4*>(ew + (size_t)bidx * C_);
    float4 al = make_float4(0.f, 0.f, 0.f, 0.f);
#pragma unroll
    for (int c4 = 0; c4 < 16; c4++) {
        float4 e = __ldg(erow + c4);
        float dx = e.x - zr[c4].x; al.x = fmaf(dx, dx, al.x);
        float dy = e.y - zr[c4].y; al.y = fmaf(dy, dy, al.y);
        float dz = e.z - zr[c4].z; al.z = fmaf(dz, dz, al.z);
        float dw = e.w - zr[c4].w; al.w = fmaf(dw, dw, al.w);
    }
    sred[tid] = (al.x + al.y) + (al.z + al.w);
    __syncthreads();                 // also publishes sidx[]
#pragma unroll
    for (int s = TPB / 2; s > 0; s >>= 1) {
        if (tid < s) sred[tid] += sred[tid + s];
        __syncthreads();
    }
    if (tid == 0) g_partials[blockIdx.x] = sred[0];

    // Quantized output (straight-through rounding replicated: z + (q - z)),
    // written transposed back to (B,C,H,W) with coalesced stores.
    const size_t obase = (size_t)b * CHW_ + hw0;
    for (int i = tid; i < TPB * C_; i += TPB) {
        int c = i >> 7;              // i / TPB
        int p = i & (TPB - 1);       // i % TPB
        float qv = ew[(size_t)sidx[p] * C_ + c];
        size_t gi = obase + (size_t)c * HW_ + p;
        float zv = z[gi];
        out[gi] = zv + (qv - zv);
    }

    // Indices output (as float), if the output buffer includes them
    if ((long long)out_size >= (long long)NPTS * C_ + NPTS)
        out[(size_t)NPTS * C_ + p0 + tid] = (float)bidx;
}

// ---------------------------------------------------------------------------
// Deterministic final loss reduction (fixed-order double tree)
// ---------------------------------------------------------------------------
__global__ void loss_kernel(float* __restrict__ out, int out_size) {
    __shared__ double sd[256];
    int tid = threadIdx.x;
    double s = 0.0;
#pragma unroll
    for (int j = 0; j < NBLK / 256; j++)
        s += (double)g_partials[tid * (NBLK / 256) + j];
    sd[tid] = s;
    __syncthreads();
#pragma unroll
    for (int st = 128; st > 0; st >>= 1) {
        if (tid < st) sd[tid] += sd[tid + st];
        __syncthreads();
    }
    if (tid == 0 && (long long)out_size >= (long long)NPTS * C_ + NPTS + 1)
        out[(size_t)NPTS * C_ + NPTS] =
            (float)(0.25 * sd[0] / (double)((size_t)NPTS * C_));
}

// ---------------------------------------------------------------------------
extern "C" void kernel_launch(void* const* d_in, const int* in_sizes, int n_in,
                              void* d_out, int out_size)
{
    const float* z  = (const float*)d_in[0];   // (32, 64, 64, 64) f32
    const float* ew = (const float*)d_in[1];   // (2048, 64) f32
    float* out = (float*)d_out;

    ee_kernel<<<(K_ + 127) / 128, 128>>>(ew);
    vq_kernel<<<NBLK, TPB>>>(z, ew, out, out_size);
    loss_kernel<<<1, 256>>>(out, out_size);
}

// round 3
// speedup vs baseline: 1.0827x; 1.0827x over previous
#include <cuda_runtime.h>
#include <math_constants.h>

// Problem constants (from reference)
#define B_    32
#define C_    64
#define H_    64
#define W_    64
#define HW_   (H_*W_)          // 4096
#define CHW_  (C_*HW_)         // 262144
#define NPTS  (B_*HW_)         // 131072 points
#define K_    2048             // codebook entries
#define TPB   128              // threads per block == points per block
#define NBLK  (NPTS/TPB)       // 1024 blocks
#define TK    128              // codes per smem tile

// Scratch (no allocations allowed)
__device__ float g_ee[K_];          // ||e_k||^2
__device__ float g_partials[NBLK];  // per-block loss partial sums

// Packed fp32x2 FMA: two independent IEEE fp32 RN FMAs per issue slot (FFMA2).
__device__ __forceinline__ void ffma2(unsigned long long& acc,
                                      unsigned long long a,
                                      unsigned long long b) {
    asm("fma.rn.f32x2 %0, %1, %2, %0;" : "+l"(acc) : "l"(a), "l"(b));
}
__device__ __forceinline__ void unpack2(unsigned long long v, float& lo, float& hi) {
    asm("mov.b64 {%0, %1}, %2;" : "=f"(lo), "=f"(hi) : "l"(v));
}
__device__ __forceinline__ unsigned long long pack2(float lo, float hi) {
    unsigned long long v;
    asm("mov.b64 %0, {%1, %2};" : "=l"(v) : "f"(lo), "f"(hi));
    return v;
}

// ---------------------------------------------------------------------------
// Precompute ||e_k||^2
// ---------------------------------------------------------------------------
__global__ void ee_kernel(const float* __restrict__ ew) {
    int k = blockIdx.x * blockDim.x + threadIdx.x;
    if (k >= K_) return;
    const float4* r = reinterpret_cast<const float4*>(ew + (size_t)k * C_);
    float4 a = make_float4(0.f, 0.f, 0.f, 0.f);
#pragma unroll
    for (int c4 = 0; c4 < 16; c4++) {
        float4 e = r[c4];
        a.x = fmaf(e.x, e.x, a.x);
        a.y = fmaf(e.y, e.y, a.y);
        a.z = fmaf(e.z, e.z, a.z);
        a.w = fmaf(e.w, e.w, a.w);
    }
    g_ee[k] = (a.x + a.y) + (a.z + a.w);
}

// ---------------------------------------------------------------------------
// Main VQ kernel: one thread per spatial point, codebook tiled through smem.
// Distances via packed FFMA2; per-lane rounding identical to the fp32
// reference: 4 accumulator lanes, final (ax+ay)+(az+aw), d = (zz+ee)-2*dot
// single-rounded, strict '<' ascending-k argmin (first-occurrence tiebreak).
// ---------------------------------------------------------------------------
__global__ __launch_bounds__(TPB)
void vq_kernel(const float* __restrict__ z, const float* __restrict__ ew,
               float* __restrict__ out, int out_size)
{
    __shared__ __align__(16) float es[TK * C_];   // 32 KB code tile
    __shared__ float see[TK];
    __shared__ float sred[TPB];
    __shared__ int   sidx[TPB];

    const int tid = threadIdx.x;
    const int p0  = blockIdx.x * TPB;
    const int b   = p0 / HW_;
    const int hw0 = p0 - b * HW_;
    const float* zp = z + (size_t)b * CHW_ + (hw0 + tid);

    // Load this thread's point: 64 channels, stride HW_, packed as 32 f32x2.
    // zll[2*c4]   = (c=4c4+0, c=4c4+1)  -> accumulates lanes (a.x, a.y)
    // zll[2*c4+1] = (c=4c4+2, c=4c4+3)  -> accumulates lanes (a.z, a.w)
    unsigned long long zll[32];
#pragma unroll
    for (int c4 = 0; c4 < 16; c4++) {
        float x = zp[(size_t)(4*c4 + 0) * HW_];
        float y = zp[(size_t)(4*c4 + 1) * HW_];
        float zc = zp[(size_t)(4*c4 + 2) * HW_];
        float w = zp[(size_t)(4*c4 + 3) * HW_];
        zll[2*c4]     = pack2(x, y);
        zll[2*c4 + 1] = pack2(zc, w);
    }

    // zz = ||z||^2, same lane structure as reference match
    unsigned long long az0 = 0ull, az1 = 0ull;   // {0.0f,0.0f}
#pragma unroll
    for (int c4 = 0; c4 < 16; c4++) {
        ffma2(az0, zll[2*c4],     zll[2*c4]);
        ffma2(az1, zll[2*c4 + 1], zll[2*c4 + 1]);
    }
    float zx, zy, zz2, zw;
    unpack2(az0, zx, zy);
    unpack2(az1, zz2, zw);
    const float zz = (zx + zy) + (zz2 + zw);

    float best = CUDART_INF_F;
    int   bidx = 0;

    for (int k0 = 0; k0 < K_; k0 += TK) {
        __syncthreads();
#pragma unroll 8
        for (int j = 0; j < (TK * C_) / TPB; j++)
            es[j * TPB + tid] = ew[(size_t)k0 * C_ + j * TPB + tid];
        see[tid] = g_ee[k0 + tid];
        __syncthreads();

#pragma unroll 2
        for (int k = 0; k < TK; k++) {
            const ulonglong2* er = reinterpret_cast<const ulonglong2*>(es + k * C_);
            unsigned long long a0 = 0ull, a1 = 0ull;
#pragma unroll
            for (int c4 = 0; c4 < 16; c4++) {
                ulonglong2 e = er[c4];   // 128-bit broadcast LDS
                ffma2(a0, zll[2*c4],     e.x);
                ffma2(a1, zll[2*c4 + 1], e.y);
            }
            float ax, ay, az2, aw;
            unpack2(a0, ax, ay);
            unpack2(a1, az2, aw);
            float dot = (ax + ay) + (az2 + aw);
            // (zz+ee) - 2*dot: 2*dot exact, one rounding on the subtract
            float d = fmaf(-2.0f, dot, zz + see[k]);
            if (d < best) { best = d; bidx = k0 + k; }
        }
    }

    sidx[tid] = bidx;

    // Commitment-loss partial: sum_c (e[bidx][c] - z[c])^2
    const float4* erow = reinterpret_cast<const float4*>(ew + (size_t)bidx * C_);
    float4 al = make_float4(0.f, 0.f, 0.f, 0.f);
#pragma unroll
    for (int c4 = 0; c4 < 16; c4++) {
        float4 e = __ldg(erow + c4);
        float l0, l1, l2, l3;
        unpack2(zll[2*c4],     l0, l1);
        unpack2(zll[2*c4 + 1], l2, l3);
        float dx = e.x - l0; al.x = fmaf(dx, dx, al.x);
        float dy = e.y - l1; al.y = fmaf(dy, dy, al.y);
        float dz = e.z - l2; al.z = fmaf(dz, dz, al.z);
        float dw = e.w - l3; al.w = fmaf(dw, dw, al.w);
    }
    sred[tid] = (al.x + al.y) + (al.z + al.w);
    __syncthreads();
#pragma unroll
    for (int s = TPB / 2; s > 0; s >>= 1) {
        if (tid < s) sred[tid] += sred[tid + s];
        __syncthreads();
    }
    if (tid == 0) g_partials[blockIdx.x] = sred[0];

    // Quantized output (straight-through rounding: z + (q - z)), transposed
    // back to (B,C,H,W), coalesced stores.
    const size_t obase = (size_t)b * CHW_ + hw0;
    for (int i = tid; i < TPB * C_; i += TPB) {
        int c = i >> 7;
        int p = i & (TPB - 1);
        float qv = ew[(size_t)sidx[p] * C_ + c];
        size_t gi = obase + (size_t)c * HW_ + p;
        float zv = z[gi];
        out[gi] = zv + (qv - zv);
    }

    if ((long long)out_size >= (long long)NPTS * C_ + NPTS)
        out[(size_t)NPTS * C_ + p0 + tid] = (float)bidx;
}

// ---------------------------------------------------------------------------
// Deterministic final loss reduction
// ---------------------------------------------------------------------------
__global__ void loss_kernel(float* __restrict__ out, int out_size) {
    __shared__ double sd[256];
    int tid = threadIdx.x;
    double s = 0.0;
#pragma unroll
    for (int j = 0; j < NBLK / 256; j++)
        s += (double)g_partials[tid * (NBLK / 256) + j];
    sd[tid] = s;
    __syncthreads();
#pragma unroll
    for (int st = 128; st > 0; st >>= 1) {
        if (tid < st) sd[tid] += sd[tid + st];
        __syncthreads();
    }
    if (tid == 0 && (long long)out_size >= (long long)NPTS * C_ + NPTS + 1)
        out[(size_t)NPTS * C_ + NPTS] =
            (float)(0.25 * sd[0] / (double)((size_t)NPTS * C_));
}

// ---------------------------------------------------------------------------
extern "C" void kernel_launch(void* const* d_in, const int* in_sizes, int n_in,
                              void* d_out, int out_size)
{
    const float* z  = (const float*)d_in[0];   // (32, 64, 64, 64) f32
    const float* ew = (const float*)d_in[1];   // (2048, 64) f32
    float* out = (float*)d_out;

    ee_kernel<<<(K_ + 127) / 128, 128>>>(ew);
    vq_kernel<<<NBLK, TPB>>>(z, ew, out, out_size);
    loss_kernel<<<1, 256>>>(out, out_size);
}